// round 16
// baseline (speedup 1.0000x reference)
#include <cuda_runtime.h>
#include <math.h>
#include <stdint.h>

#define B_ 4
#define N_ 2048
#define E_ 1024
#define H_ 16
#define D_ 64
#define M_ (B_*N_)   // 8192

// Scratch.  NOTE: g_V is stored TRANSPOSED per (b,h): [b,h,d,n]
__device__ float g_Q[(size_t)B_*H_*N_*D_];
__device__ float g_K[(size_t)B_*H_*N_*D_];
__device__ float g_V[(size_t)B_*H_*N_*D_];
__device__ float g_A[(size_t)B_*H_*N_*D_];
__device__ float g_X[(size_t)M_*E_];          // pre-rounded x
__device__ float g_W4[4][(size_t)E_*E_];      // pre-rounded Wq,Wk,Wv,Wo

// ---------------------------------------------------------------------------
// helpers
// ---------------------------------------------------------------------------
__device__ __forceinline__ uint32_t f2tf(float x) {
    uint32_t u;
    asm("cvt.rna.tf32.f32 %0, %1;" : "=r"(u) : "f"(x));
    return u;
}
__device__ __forceinline__ float rndf(float x) { return __uint_as_float(f2tf(x)); }

__device__ __forceinline__ void mma8(float* c, const uint32_t* a, const uint32_t* b) {
    asm volatile(
        "mma.sync.aligned.m16n8k8.row.col.f32.tf32.tf32.f32 "
        "{%0,%1,%2,%3}, {%4,%5,%6,%7}, {%8,%9}, {%0,%1,%2,%3};"
        : "+f"(c[0]), "+f"(c[1]), "+f"(c[2]), "+f"(c[3])
        : "r"(a[0]), "r"(a[1]), "r"(a[2]), "r"(a[3]), "r"(b[0]), "r"(b[1]));
}

__device__ __forceinline__ void ldsm4(uint32_t* r, uint32_t addr) {
    asm volatile("ldmatrix.sync.aligned.m8n8.x4.shared.b16 {%0,%1,%2,%3}, [%4];"
                 : "=r"(r[0]), "=r"(r[1]), "=r"(r[2]), "=r"(r[3]) : "r"(addr));
}

__device__ __forceinline__ uint32_t smem_u32(const void* p) {
    uint32_t a;
    asm("{ .reg .u64 t; cvta.to.shared.u64 t, %1; cvt.u32.u64 %0, t; }" : "=r"(a) : "l"(p));
    return a;
}
__device__ __forceinline__ void cp16(uint32_t dst, const void* src) {
    size_t g = __cvta_generic_to_global(src);
    asm volatile("cp.async.cg.shared.global [%0], [%1], 16;" :: "r"(dst), "l"(g));
}
#define CP_COMMIT() asm volatile("cp.async.commit_group;" ::: "memory")
#define CP_WAIT0()  asm volatile("cp.async.wait_group 0;" ::: "memory")
#define CP_WAIT1()  asm volatile("cp.async.wait_group 1;" ::: "memory")

// ---------------------------------------------------------------------------
// Pre-round passes
// ---------------------------------------------------------------------------
__global__ void round_x(const float* __restrict__ src, int n4) {
    int i = blockIdx.x * blockDim.x + threadIdx.x;
    if (i < n4) {
        float4 v = ((const float4*)src)[i];
        v.x = rndf(v.x); v.y = rndf(v.y); v.z = rndf(v.z); v.w = rndf(v.w);
        ((float4*)g_X)[i] = v;
    }
}

__global__ void round_w(const float* __restrict__ wq, const float* __restrict__ wk,
                        const float* __restrict__ wv, const float* __restrict__ wo) {
    const float* src;
    switch (blockIdx.y) {
        case 0: src = wq; break;
        case 1: src = wk; break;
        case 2: src = wv; break;
        default: src = wo; break;
    }
    int i = blockIdx.x * blockDim.x + threadIdx.x;
    float4 v = ((const float4*)src)[i];
    v.x = rndf(v.x); v.y = rndf(v.y); v.z = rndf(v.z); v.w = rndf(v.w);
    ((float4*)g_W4[blockIdx.y])[i] = v;
}

// ---------------------------------------------------------------------------
// Projection GEMM core: C[128m x 128n] = A[m,k] * W[n,k]^T + bias
// 3-stage cp.async ring, BK=32, pad-36 rows, ldmatrix fragment loads.
// out_mode: 0 = linear [m][E]; 1 = scatter [b,h,n,d]; 2 = scatter transposed [b,h,d,n]
// ---------------------------------------------------------------------------
template<bool GATHER_A>
__device__ __forceinline__ void proj_core(
    const float* __restrict__ Ap, const float* __restrict__ Wp,
    const float* __restrict__ bias, float* __restrict__ outp,
    float oscale, bool oround, int out_mode)
{
    extern __shared__ float smf[];
    float* AsBuf = smf;              // 3 x 4608
    float* BsBuf = smf + 13824;      // 3 x 4608
    const uint32_t As_u = smem_u32(AsBuf);
    const uint32_t Bs_u = smem_u32(BsBuf);

    const int tid  = threadIdx.x;
    const int wid  = tid >> 5;
    const int lane = tid & 31;
    const int g    = lane >> 2;
    const int tg   = lane & 3;
    const int mat  = lane >> 3;
    const int mr   = lane & 7;
    const int mw   = wid & 3;
    const int nw   = wid >> 2;

    // per-lane ldmatrix offsets (bytes), row stride 36 floats
    const uint32_t a_loff = (uint32_t)((((mat & 1)*8 + mr)*36 + (mat >> 1)*4) * 4);
    const uint32_t b_loff = (uint32_t)((((mat >> 1)*8 + mr)*36 + (mat & 1)*4) * 4);

    const int m0 = blockIdx.x * 128;
    const int o0 = blockIdx.y * 128;

    const int lr = tid >> 3;          // 0..31
    const int lk = (tid & 7) * 4;     // 0..28

    auto issue = [&](int it, int st) {
        const int k = it * 32 + lk;
        #pragma unroll
        for (int p = 0; p < 4; p++) {
            const int row = lr + p * 32;
            const float* sa;
            if (GATHER_A) {
                int m = m0 + row, bb = m >> 11, n = m & (N_-1);
                int hh = k >> 6, dd = k & 63;
                sa = &g_A[(((size_t)(bb*H_ + hh))*N_ + n)*D_ + dd];
            } else {
                sa = &Ap[(size_t)(m0 + row)*E_ + k];
            }
            cp16(As_u + (uint32_t)(st*18432) + (uint32_t)((row*36 + lk)*4), sa);
            cp16(Bs_u + (uint32_t)(st*18432) + (uint32_t)((row*36 + lk)*4),
                 &Wp[(size_t)(o0 + row)*E_ + k]);
        }
        CP_COMMIT();
    };

    float cacc[2][8][4] = {};

    issue(0, 0);
    issue(1, 1);

    int st = 0;
    for (int it = 0; it < 32; ++it) {
        if (it == 31) CP_WAIT0(); else CP_WAIT1();
        __syncthreads();
        if (it + 2 < 32) {
            int st2 = st + 2; if (st2 >= 3) st2 -= 3;
            issue(it + 2, st2);
        }

        const uint32_t Au_u = As_u + (uint32_t)(st*18432);
        const uint32_t Bu_u = Bs_u + (uint32_t)(st*18432);
        #pragma unroll
        for (int kb = 0; kb < 4; kb++) {
            uint32_t af[2][4];
            ldsm4(af[0], Au_u + (uint32_t)(((mw*32     )*36 + kb*8)*4) + a_loff);
            ldsm4(af[1], Au_u + (uint32_t)(((mw*32 + 16)*36 + kb*8)*4) + a_loff);
            #pragma unroll
            for (int nbp = 0; nbp < 4; nbp++) {
                uint32_t bb[4];
                ldsm4(bb, Bu_u + (uint32_t)(((nw*64 + nbp*16)*36 + kb*8)*4) + b_loff);
                mma8(cacc[0][2*nbp    ], af[0], bb);
                mma8(cacc[0][2*nbp + 1], af[0], bb + 2);
                mma8(cacc[1][2*nbp    ], af[1], bb);
                mma8(cacc[1][2*nbp + 1], af[1], bb + 2);
            }
        }
        if (++st == 3) st = 0;
    }

    // ---- epilogue ----
    #pragma unroll
    for (int mi = 0; mi < 2; mi++) {
        int r0 = m0 + mw*32 + mi*16 + g;
        #pragma unroll
        for (int nb = 0; nb < 8; nb++) {
            int gcol = o0 + nw*64 + nb*8 + 2*tg;
            float b0 = bias[gcol], b1 = bias[gcol + 1];
            float2 v0 = { (cacc[mi][nb][0] + b0)*oscale, (cacc[mi][nb][1] + b1)*oscale };
            float2 v1 = { (cacc[mi][nb][2] + b0)*oscale, (cacc[mi][nb][3] + b1)*oscale };
            if (oround) {
                v0.x = rndf(v0.x); v0.y = rndf(v0.y);
                v1.x = rndf(v1.x); v1.y = rndf(v1.y);
            }
            int r1 = r0 + 8;
            if (out_mode == 1) {
                int hh = gcol >> 6, dd = gcol & 63;
                int bb0 = r0 >> 11, n0 = r0 & (N_-1);
                int bb1 = r1 >> 11, n1 = r1 & (N_-1);
                *(float2*)&outp[(((size_t)(bb0*H_ + hh))*N_ + n0)*D_ + dd] = v0;
                *(float2*)&outp[(((size_t)(bb1*H_ + hh))*N_ + n1)*D_ + dd] = v1;
            } else if (out_mode == 2) {
                int hh = gcol >> 6, dd = gcol & 63;
                int bb0 = r0 >> 11, n0 = r0 & (N_-1);
                int bb1 = r1 >> 11, n1 = r1 & (N_-1);
                float* b0p = &outp[((size_t)(bb0*H_ + hh)*D_ + dd)*N_ + n0];
                float* b1p = &outp[((size_t)(bb1*H_ + hh)*D_ + dd)*N_ + n1];
                b0p[0] = v0.x; b0p[N_] = v0.y;
                b1p[0] = v1.x; b1p[N_] = v1.y;
            } else {
                *(float2*)&outp[(size_t)r0*E_ + gcol] = v0;
                *(float2*)&outp[(size_t)r1*E_ + gcol] = v1;
            }
        }
    }
}

__global__ void __launch_bounds__(256, 2) qkv_tc2(
    const float* __restrict__ bq, const float* __restrict__ bk,
    const float* __restrict__ bv)
{
    const float* W; const float* bias; float* out; float sc; int mode;
    if (blockIdx.z == 0)      { W = g_W4[0]; bias = bq; out = g_Q; sc = 0.125f; mode = 1; }
    else if (blockIdx.z == 1) { W = g_W4[1]; bias = bk; out = g_K; sc = 1.f;    mode = 1; }
    else                      { W = g_W4[2]; bias = bv; out = g_V; sc = 1.f;    mode = 2; }
    proj_core<false>(g_X, W, bias, out, sc, true, mode);
}

__global__ void __launch_bounds__(256, 2) oproj_tc(
    const float* __restrict__ bo, float* __restrict__ out)
{
    proj_core<true>(nullptr, g_W4[3], bo, out, 1.f, false, 0);
}

// ---------------------------------------------------------------------------
// Attention: per (b, h, 128-q tile). 8 warps x 16 q-rows. kv tiles of 64,
// 3-stage cp.async ring, ldmatrix K/V fragments (double-buffered), V transposed.
// P re-fragmented via register shuffles (double-buffered, no smem round-trip).
// sc seeded with distance bias so dist LDGs overlap the S-MMA block.
// ---------------------------------------------------------------------------
__global__ void __launch_bounds__(256, 2) attn_tc(
    const float* __restrict__ dist,
    const float* __restrict__ dwp, const float* __restrict__ dbp)
{
    extern __shared__ float smf[];
    // stage s (s=0..2): K at s*8704 floats [kv=64][68], Vt at +4352 [d=64][68]
    const uint32_t sm_u = smem_u32(smf);

    const int tid  = threadIdx.x;
    const int wid  = tid >> 5;
    const int lane = tid & 31;
    const int g    = lane >> 2;
    const int tg   = lane & 3;
    const int mat  = lane >> 3;
    const int mr   = lane & 7;

    // per-lane ldmatrix offset (bytes), row stride 68 floats (B-fragments)
    const uint32_t kv_loff = (uint32_t)((((mat >> 1)*8 + mr)*68 + (mat & 1)*4) * 4);

    // shfl sources for P re-fragmentation
    const int srcA = g*4 + (tg >> 1);
    const int srcB = srcA + 2;
    const bool podd = (tg & 1);

    const int q0 = blockIdx.x * 128;
    const int h  = blockIdx.y;
    const int b  = blockIdx.z;
    const size_t base = ((size_t)(b*H_ + h)) * N_ * D_;
    const float* Qp  = g_Q + base;   // [n][d]
    const float* Kp  = g_K + base;   // [n][d]
    const float* Vtp = g_V + base;   // [d][n]  (transposed)
    float*       Op  = g_A + base;   // [n][d]

    const float dw = dwp[0], db = dbp[0];
    const int qr0 = q0 + wid*16 + g;
    const int qr1 = qr0 + 8;

    const int lrow = tid >> 2;         // 0..63
    const int lc   = (tid & 3) * 16;   // float offset

    auto issue_kv = [&](int kt, int stg) {
        const int kv0 = kt * 64;
        const uint32_t kb_u = sm_u + (uint32_t)(stg * 34816);
        #pragma unroll
        for (int j = 0; j < 4; j++) {
            cp16(kb_u          + (uint32_t)((lrow*68 + lc + 4*j)*4),
                 &Kp[(size_t)(kv0 + lrow)*D_ + lc + 4*j]);
            cp16(kb_u + 17408u + (uint32_t)((lrow*68 + lc + 4*j)*4),
                 &Vtp[(size_t)lrow*N_ + kv0 + lc + 4*j]);
        }
        CP_COMMIT();
    };

    auto shuffle_pa = [&](uint32_t* pa, const uint32_t* pk) {
        uint32_t p0 = __shfl_sync(0xffffffffu, pk[0], srcA);
        uint32_t p1 = __shfl_sync(0xffffffffu, pk[1], srcA);
        uint32_t p2 = __shfl_sync(0xffffffffu, pk[2], srcA);
        uint32_t p3 = __shfl_sync(0xffffffffu, pk[3], srcA);
        uint32_t r0 = __shfl_sync(0xffffffffu, pk[0], srcB);
        uint32_t r1 = __shfl_sync(0xffffffffu, pk[1], srcB);
        uint32_t r2 = __shfl_sync(0xffffffffu, pk[2], srcB);
        uint32_t r3 = __shfl_sync(0xffffffffu, pk[3], srcB);
        pa[0] = podd ? p1 : p0;   // P[qr0][kb*8+tg]
        pa[1] = podd ? p3 : p2;   // P[qr1][kb*8+tg]
        pa[2] = podd ? r1 : r0;   // P[qr0][kb*8+tg+4]
        pa[3] = podd ? r3 : r2;   // P[qr1][kb*8+tg+4]
    };

    issue_kv(0, 0);
    issue_kv(1, 1);

    // Q fragments (already tf32-rounded & 0.125-scaled)
    uint32_t qa[8][4];
    #pragma unroll
    for (int kb = 0; kb < 8; kb++) {
        int c = kb*8 + tg;
        qa[kb][0] = __float_as_uint(Qp[(size_t)qr0*D_ + c        ]);
        qa[kb][1] = __float_as_uint(Qp[(size_t)qr1*D_ + c        ]);
        qa[kb][2] = __float_as_uint(Qp[(size_t)qr0*D_ + c + 4    ]);
        qa[kb][3] = __float_as_uint(Qp[(size_t)qr1*D_ + c + 4    ]);
    }

    float oc[8][4] = {};
    float mh0 = -INFINITY, mh1 = -INFINITY;
    float lh0 = 0.f, lh1 = 0.f;

    int stg = 0;
    for (int kt = 0; kt < 32; kt++) {
        const int kv0 = kt * 64;
        if (kt == 31) CP_WAIT0(); else CP_WAIT1();
        __syncthreads();
        if (kt + 2 < 32) {
            int s2 = stg + 2; if (s2 >= 3) s2 -= 3;
            issue_kv(kt + 2, s2);
        }

        const uint32_t Ks_u = sm_u + (uint32_t)(stg * 34816);
        const uint32_t Vs_u = Ks_u + 17408u;

        // ---- seed sc with distance bias (LDGs overlap the S MMAs below) ----
        float sc[8][4];
        #pragma unroll
        for (int nb = 0; nb < 8; nb++) {
            int col = kv0 + nb*8 + 2*tg;
            float2 d0 = *(const float2*)&dist[(size_t)qr0*N_ + col];
            float2 d1 = *(const float2*)&dist[(size_t)qr1*N_ + col];
            sc[nb][0] = fmaf(dw, d0.x, db);
            sc[nb][1] = fmaf(dw, d0.y, db);
            sc[nb][2] = fmaf(dw, d1.x, db);
            sc[nb][3] = fmaf(dw, d1.y, db);
        }

        // ---- S = (Q/8) K^T + bias : double-buffered K fragments ----
        {
            uint32_t bbA[4], bbB[4];
            ldsm4(bbA, Ks_u + kv_loff);       // t=0: kb=0, nbp=0
            #pragma unroll
            for (int t = 0; t < 32; t++) {
                uint32_t* cur = (t & 1) ? bbB : bbA;
                uint32_t* nxt = (t & 1) ? bbA : bbB;
                if (t < 31) {
                    int kb2 = (t + 1) >> 2, nbp2 = (t + 1) & 3;
                    ldsm4(nxt, Ks_u + (uint32_t)((nbp2*16*68 + kb2*8)*4) + kv_loff);
                }
                int kb = t >> 2, nbp = t & 3;
                mma8(sc[2*nbp    ], qa[kb], cur);
                mma8(sc[2*nbp + 1], qa[kb], cur + 2);
            }
        }

        // ---- online softmax (rows qr0 / qr1, stats shared across lane quad) ----
        float mt0 = -INFINITY, mt1 = -INFINITY;
        #pragma unroll
        for (int nb = 0; nb < 8; nb++) {
            mt0 = fmaxf(mt0, fmaxf(sc[nb][0], sc[nb][1]));
            mt1 = fmaxf(mt1, fmaxf(sc[nb][2], sc[nb][3]));
        }
        mt0 = fmaxf(mt0, __shfl_xor_sync(0xffffffffu, mt0, 1));
        mt0 = fmaxf(mt0, __shfl_xor_sync(0xffffffffu, mt0, 2));
        mt1 = fmaxf(mt1, __shfl_xor_sync(0xffffffffu, mt1, 1));
        mt1 = fmaxf(mt1, __shfl_xor_sync(0xffffffffu, mt1, 2));
        float mn0 = fmaxf(mh0, mt0), mn1 = fmaxf(mh1, mt1);
        float corr0 = __expf(mh0 - mn0), corr1 = __expf(mh1 - mn1);
        float s0 = 0.f, s1 = 0.f;
        #pragma unroll
        for (int nb = 0; nb < 8; nb++) {
            sc[nb][0] = __expf(sc[nb][0] - mn0); s0 += sc[nb][0];
            sc[nb][1] = __expf(sc[nb][1] - mn0); s0 += sc[nb][1];
            sc[nb][2] = __expf(sc[nb][2] - mn1); s1 += sc[nb][2];
            sc[nb][3] = __expf(sc[nb][3] - mn1); s1 += sc[nb][3];
        }
        s0 += __shfl_xor_sync(0xffffffffu, s0, 1);
        s0 += __shfl_xor_sync(0xffffffffu, s0, 2);
        s1 += __shfl_xor_sync(0xffffffffu, s1, 1);
        s1 += __shfl_xor_sync(0xffffffffu, s1, 2);
        lh0 = lh0*corr0 + s0;
        lh1 = lh1*corr1 + s1;
        mh0 = mn0; mh1 = mn1;
        #pragma unroll
        for (int nb = 0; nb < 8; nb++) {
            oc[nb][0] *= corr0; oc[nb][1] *= corr0;
            oc[nb][2] *= corr1; oc[nb][3] *= corr1;
        }

        // ---- round P to tf32 in place (C-fragment layout) ----
        uint32_t pu[8][4];
        #pragma unroll
        for (int nb = 0; nb < 8; nb++) {
            pu[nb][0] = f2tf(sc[nb][0]);
            pu[nb][1] = f2tf(sc[nb][1]);
            pu[nb][2] = f2tf(sc[nb][2]);
            pu[nb][3] = f2tf(sc[nb][3]);
        }

        // ---- O += P V : double-buffered pa (shuffles) and V fragments ----
        {
            uint32_t paA[4], paB[4];
            shuffle_pa(paA, pu[0]);
            uint32_t vbA[4], vbB[4];
            ldsm4(vbA, Vs_u + kv_loff);       // t=0: kb=0, nbp=0
            #pragma unroll
            for (int t = 0; t < 32; t++) {
                int kb = t >> 2, nbp = t & 3;
                uint32_t* vcur = (t & 1) ? vbB : vbA;
                uint32_t* vnxt = (t & 1) ? vbA : vbB;
                if (t < 31) {
                    int kb2 = (t + 1) >> 2, nbp2 = (t + 1) & 3;
                    ldsm4(vnxt, Vs_u + (uint32_t)((nbp2*16*68 + kb2*8)*4) + kv_loff);
                }
                uint32_t* pcur = (kb & 1) ? paB : paA;
                if (nbp == 0 && kb < 7) {
                    shuffle_pa((kb & 1) ? paA : paB, pu[kb + 1]);
                }
                mma8(oc[2*nbp    ], pcur, vcur);
                mma8(oc[2*nbp + 1], pcur, vcur + 2);
            }
        }

        if (++stg == 3) stg = 0;
    }

    // ---- normalize + store (tf32-rounded for oproj's A operand) ----
    const float inv0 = 1.f / lh0, inv1 = 1.f / lh1;
    #pragma unroll
    for (int nb = 0; nb < 8; nb++) {
        int c = nb*8 + 2*tg;
        float2 v0 = { rndf(oc[nb][0]*inv0), rndf(oc[nb][1]*inv0) };
        float2 v1 = { rndf(oc[nb][2]*inv1), rndf(oc[nb][3]*inv1) };
        *(float2*)&Op[(size_t)qr0*D_ + c] = v0;
        *(float2*)&Op[(size_t)qr1*D_ + c] = v1;
    }
}

// ---------------------------------------------------------------------------
extern "C" void kernel_launch(void* const* d_in, const int* in_sizes, int n_in,
                              void* d_out, int out_size)
{
    const float* x    = (const float*)d_in[0];
    const float* dist = (const float*)d_in[1];
    const float* Wq   = (const float*)d_in[2];
    const float* bq   = (const float*)d_in[3];
    const float* Wk   = (const float*)d_in[4];
    const float* bk   = (const float*)d_in[5];
    const float* Wv   = (const float*)d_in[6];
    const float* bv   = (const float*)d_in[7];
    const float* Wo   = (const float*)d_in[8];
    const float* bo   = (const float*)d_in[9];
    const float* dw   = (const float*)d_in[10];
    const float* db   = (const float*)d_in[11];
    float* out = (float*)d_out;

    const int nx4 = M_*E_/4, nw4 = E_*E_/4;
    round_x<<<(nx4 + 255)/256, 256>>>(x, nx4);
    round_w<<<dim3(nw4/256, 4), 256>>>(Wq, Wk, Wv, Wo);

    const int proj_smem = 27648 * (int)sizeof(float);   // 110592 B
    const int attn_smem = 26112 * (int)sizeof(float);   // 104448 B (3 stages)
    cudaFuncSetAttribute(qkv_tc2, cudaFuncAttributeMaxDynamicSharedMemorySize, proj_smem);
    cudaFuncSetAttribute(oproj_tc, cudaFuncAttributeMaxDynamicSharedMemorySize, proj_smem);
    cudaFuncSetAttribute(attn_tc, cudaFuncAttributeMaxDynamicSharedMemorySize, attn_smem);

    qkv_tc2<<<dim3(M_/128, E_/128, 3), 256, proj_smem>>>(bq, bk, bv);
    attn_tc<<<dim3(N_/128, H_, B_), 256, attn_smem>>>(dist, dw, db);
    oproj_tc<<<dim3(M_/128, E_/128), 256, proj_smem>>>(bo, out);
}